// round 1
// baseline (speedup 1.0000x reference)
#include <cuda_runtime.h>
#include <cuda_bf16.h>

// Problem constants
#define Bt 2
#define Tt 2048
#define Cc 1024
#define Hh 16
#define Dd 64
#define N3 (3 * Cc)          // 3072
#define Mm (Bt * Tt)         // 4096
#define ATT_SCALE (0.1f / 8.0f)   // 0.1 / sqrt(64)

// Scratch (allocation-free rule: __device__ globals)
__device__ float g_qkv[(size_t)Mm * N3];   // [4096, 3072]
__device__ float g_y[(size_t)Mm * Cc];     // [4096, 1024]

// ---------------------------------------------------------------------------
// SGEMM + bias: C[M,N] = A[M,K] @ B[K,N] + bias[N]
// BM=BN=128, BK=16, 256 threads, 8x8 per-thread tile.
// M,N,K are multiples of the tile sizes here (4096 / 3072|1024 / 1024).
// ---------------------------------------------------------------------------
__global__ __launch_bounds__(256) void sgemm_bias_kernel(
    const float* __restrict__ A, const float* __restrict__ Bm,
    const float* __restrict__ bias, float* __restrict__ C,
    int M, int N, int K)
{
    const int BM = 128, BN = 128, BK = 16;
    __shared__ float As[16][128];   // transposed A tile
    __shared__ float Bs[16][128];

    const int tid = threadIdx.x;
    const int bm = blockIdx.y * BM;
    const int bn = blockIdx.x * BN;
    const int tx = tid & 15;        // 16 thread cols
    const int ty = tid >> 4;        // 16 thread rows

    float acc[8][8];
#pragma unroll
    for (int i = 0; i < 8; i++)
#pragma unroll
        for (int j = 0; j < 8; j++) acc[i][j] = 0.f;

    const float* Ab = A + (size_t)bm * K;
    const float* Bb = Bm + bn;

    const int ar = tid >> 2;            // 0..63
    const int ac = (tid & 3) * 4;       // 0,4,8,12
    const int bkr = tid >> 5;           // 0..7
    const int bc = (tid & 31) * 4;      // 0..124

    for (int k0 = 0; k0 < K; k0 += BK) {
        // load A tile (128 x 16), transpose into As[k][m]
#pragma unroll
        for (int l = 0; l < 2; l++) {
            int r = ar + l * 64;
            float4 v = *(const float4*)(Ab + (size_t)r * K + k0 + ac);
            As[ac + 0][r] = v.x;
            As[ac + 1][r] = v.y;
            As[ac + 2][r] = v.z;
            As[ac + 3][r] = v.w;
        }
        // load B tile (16 x 128)
#pragma unroll
        for (int l = 0; l < 2; l++) {
            int kr = bkr + l * 8;
            *(float4*)(&Bs[kr][bc]) =
                *(const float4*)(Bb + (size_t)(k0 + kr) * N + bc);
        }
        __syncthreads();

#pragma unroll
        for (int kk = 0; kk < BK; kk++) {
            float a[8], b[8];
            float4 a0 = *(const float4*)(&As[kk][ty * 8]);
            float4 a1 = *(const float4*)(&As[kk][ty * 8 + 4]);
            float4 b0 = *(const float4*)(&Bs[kk][tx * 8]);
            float4 b1 = *(const float4*)(&Bs[kk][tx * 8 + 4]);
            a[0]=a0.x; a[1]=a0.y; a[2]=a0.z; a[3]=a0.w;
            a[4]=a1.x; a[5]=a1.y; a[6]=a1.z; a[7]=a1.w;
            b[0]=b0.x; b[1]=b0.y; b[2]=b0.z; b[3]=b0.w;
            b[4]=b1.x; b[5]=b1.y; b[6]=b1.z; b[7]=b1.w;
#pragma unroll
            for (int i = 0; i < 8; i++)
#pragma unroll
                for (int j = 0; j < 8; j++)
                    acc[i][j] += a[i] * b[j];
        }
        __syncthreads();
    }

    // epilogue + bias
#pragma unroll
    for (int i = 0; i < 8; i++) {
        int row = bm + ty * 8 + i;
        float* crow = C + (size_t)row * N + bn + tx * 8;
        const float* brow = bias + bn + tx * 8;
#pragma unroll
        for (int j = 0; j < 8; j += 4) {
            float4 o;
            o.x = acc[i][j + 0] + brow[j + 0];
            o.y = acc[i][j + 1] + brow[j + 1];
            o.z = acc[i][j + 2] + brow[j + 2];
            o.w = acc[i][j + 3] + brow[j + 3];
            *(float4*)(crow + j) = o;
        }
    }
}

// ---------------------------------------------------------------------------
// Causal flash attention, fp32.
// grid = (T/128, B*H), block = 128 threads. One thread per query row.
// q and output accumulator live in registers (16 float4 each).
// K/V processed in 64-row shared tiles; online softmax in 8-key chunks.
// ---------------------------------------------------------------------------
__global__ __launch_bounds__(128) void attn_kernel(
    const float* __restrict__ qkv, float* __restrict__ y)
{
    const int qb = blockIdx.x;           // query tile (128 rows)
    const int bh = blockIdx.y;           // 0..B*H-1
    const int b = bh >> 4;               // / 16 heads
    const int h = bh & 15;
    const int tid = threadIdx.x;
    const int qi = qb * 128 + tid;       // query row within T

    __shared__ float Ks[64][64];
    __shared__ float Vs[64][64];

    const float* base = qkv + (size_t)b * Tt * N3;

    // load q row into registers
    float4 q[16];
    {
        const float4* qrow = (const float4*)(base + (size_t)qi * N3 + h * Dd);
#pragma unroll
        for (int i = 0; i < 16; i++) q[i] = qrow[i];
    }

    float4 acc[16];
#pragma unroll
    for (int i = 0; i < 16; i++) acc[i] = make_float4(0.f, 0.f, 0.f, 0.f);
    float m = -1e30f, l = 0.f;

    const int ntiles = 2 * qb + 2;       // key tiles needed (causal)

    const int lr = tid >> 4;             // 0..7 (tile-load row base)
    const int lc = tid & 15;             // float4 col within 64-float row

#pragma unroll 1
    for (int kb = 0; kb < ntiles; kb++) {
        __syncthreads();                 // previous tile fully consumed
        // cooperative K/V tile load: 64 rows x 64 floats each
#pragma unroll
        for (int p = 0; p < 8; p++) {
            int r = lr + p * 8;
            const float* krow = base + (size_t)(kb * 64 + r) * N3 + Cc + h * Dd;
            ((float4*)Ks[r])[lc] = ((const float4*)krow)[lc];
            ((float4*)Vs[r])[lc] = ((const float4*)(krow + Cc))[lc];
        }
        __syncthreads();

#pragma unroll 1
        for (int jc = 0; jc < 64; jc += 8) {
            float s[8];
#pragma unroll
            for (int j = 0; j < 8; j++) {
                const float4* kr = (const float4*)Ks[jc + j];
                float ss = 0.f;
#pragma unroll
                for (int d = 0; d < 16; d++) {
                    float4 kk = kr[d];
                    ss += q[d].x * kk.x + q[d].y * kk.y
                        + q[d].z * kk.z + q[d].w * kk.w;
                }
                int kj = kb * 64 + jc + j;
                s[j] = (kj <= qi) ? ss * ATT_SCALE : -1e30f;
            }
            float mc = s[0];
#pragma unroll
            for (int j = 1; j < 8; j++) mc = fmaxf(mc, s[j]);
            float mnew = fmaxf(m, mc);
            float corr = __expf(m - mnew);
            m = mnew;
            l *= corr;
#pragma unroll
            for (int d = 0; d < 16; d++) {
                acc[d].x *= corr; acc[d].y *= corr;
                acc[d].z *= corr; acc[d].w *= corr;
            }
#pragma unroll
            for (int j = 0; j < 8; j++) {
                float p = __expf(s[j] - m);
                l += p;
                const float4* vr = (const float4*)Vs[jc + j];
#pragma unroll
                for (int d = 0; d < 16; d++) {
                    float4 vv = vr[d];
                    acc[d].x += p * vv.x; acc[d].y += p * vv.y;
                    acc[d].z += p * vv.z; acc[d].w += p * vv.w;
                }
            }
        }
    }

    float inv = 1.f / l;
    float4* yrow = (float4*)(y + ((size_t)b * Tt + qi) * Cc + h * Dd);
#pragma unroll
    for (int d = 0; d < 16; d++) {
        float4 o = acc[d];
        o.x *= inv; o.y *= inv; o.z *= inv; o.w *= inv;
        yrow[d] = o;
    }
}

// ---------------------------------------------------------------------------
extern "C" void kernel_launch(void* const* d_in, const int* in_sizes, int n_in,
                              void* d_out, int out_size)
{
    const float* x      = (const float*)d_in[0];
    const float* w_attn = (const float*)d_in[1];
    const float* b_attn = (const float*)d_in[2];
    const float* w_proj = (const float*)d_in[3];
    const float* b_proj = (const float*)d_in[4];
    float* out = (float*)d_out;

    void* qkv_p = nullptr;
    void* y_p = nullptr;
    cudaGetSymbolAddress(&qkv_p, g_qkv);
    cudaGetSymbolAddress(&y_p, g_y);
    float* qkv = (float*)qkv_p;
    float* y   = (float*)y_p;

    // 1) qkv = x @ w_attn + b_attn    [4096,3072]
    {
        dim3 grid(N3 / 128, Mm / 128);
        sgemm_bias_kernel<<<grid, 256>>>(x, w_attn, b_attn, qkv, Mm, N3, Cc);
    }
    // 2) causal attention -> y [4096,1024]
    {
        dim3 grid(Tt / 128, Bt * Hh);
        attn_kernel<<<grid, 128>>>(qkv, y);
    }
    // 3) out = y @ w_proj + b_proj   [4096,1024]
    {
        dim3 grid(Cc / 128, Mm / 128);
        sgemm_bias_kernel<<<grid, 256>>>(y, w_proj, b_proj, out, Mm, Cc, Cc);
    }
}

// round 2
// speedup vs baseline: 1.4375x; 1.4375x over previous
#include <cuda_runtime.h>
#include <cuda_bf16.h>

// Problem constants
#define Bt 2
#define Tt 2048
#define Cc 1024
#define Hh 16
#define Dd 64
#define N3 (3 * Cc)          // 3072
#define Mm (Bt * Tt)         // 4096
#define ATT_SCALE (0.1f / 8.0f)   // 0.1 / sqrt(64)

// Scratch (allocation-free rule: __device__ globals)
__device__ float g_qkv[(size_t)Mm * N3];   // [4096, 3072]
__device__ float g_y[(size_t)Mm * Cc];     // [4096, 1024]

__device__ __forceinline__ unsigned f2tf32(float x) {
    unsigned r;
    asm("cvt.rna.tf32.f32 %0, %1;" : "=r"(r) : "f"(x));
    return r;
}

// ---------------------------------------------------------------------------
// TF32 tensor-core GEMM + bias: C[M,N] = A[M,K] @ B[K,N] + bias[N]
// CTA tile 128x128, BK=16, 256 threads = 8 warps (2x4), warp tile 64x32.
// mma.sync.m16n8k8.tf32. Double-buffered SMEM with register prefetch.
// A smem stride 20 and B smem stride 132 -> conflict-free fragment LDS.
// ---------------------------------------------------------------------------
__global__ __launch_bounds__(256, 2) void gemm_tf32_bias_kernel(
    const float* __restrict__ A, const float* __restrict__ Bm,
    const float* __restrict__ bias, float* __restrict__ C,
    int M, int N, int K)
{
    __shared__ float As[2][128][20];   // [row][k] (only cols 0..15 used)
    __shared__ float Bs[2][16][132];   // [k][col]

    const int tid  = threadIdx.x;
    const int lane = tid & 31;
    const int warp = tid >> 5;
    const int bm = blockIdx.y * 128;
    const int bn = blockIdx.x * 128;
    const int wm = (warp >> 2) * 64;   // 0 or 64
    const int wn = (warp & 3) * 32;    // 0,32,64,96

    float acc[4][4][4];
#pragma unroll
    for (int i = 0; i < 4; i++)
#pragma unroll
        for (int j = 0; j < 4; j++)
#pragma unroll
            for (int r = 0; r < 4; r++) acc[i][j][r] = 0.f;

    // gmem load indexing (float4 granularity)
    const int a_row0 = tid >> 2;              // idx/4  (idx = i*256+tid)
    const int a_c4   = (tid & 3);             // float4 col 0..3
    const int b_row0 = tid >> 5;              // idx/32
    const int b_c4   = (tid & 31);            // float4 col 0..31

    float4 pa[2], pb[2];

    auto prefetch = [&](int k0) {
#pragma unroll
        for (int i = 0; i < 2; i++) {
            int ar = a_row0 + i * 64;
            pa[i] = *(const float4*)(A + (size_t)(bm + ar) * K + k0 + a_c4 * 4);
            int br = b_row0 + i * 8;
            pb[i] = *(const float4*)(Bm + (size_t)(k0 + br) * N + bn + b_c4 * 4);
        }
    };
    auto stage = [&](int s) {
#pragma unroll
        for (int i = 0; i < 2; i++) {
            int ar = a_row0 + i * 64;
            float4 va;
            va.x = __uint_as_float(f2tf32(pa[i].x));
            va.y = __uint_as_float(f2tf32(pa[i].y));
            va.z = __uint_as_float(f2tf32(pa[i].z));
            va.w = __uint_as_float(f2tf32(pa[i].w));
            *(float4*)(&As[s][ar][a_c4 * 4]) = va;
            int br = b_row0 + i * 8;
            float4 vb;
            vb.x = __uint_as_float(f2tf32(pb[i].x));
            vb.y = __uint_as_float(f2tf32(pb[i].y));
            vb.z = __uint_as_float(f2tf32(pb[i].z));
            vb.w = __uint_as_float(f2tf32(pb[i].w));
            *(float4*)(&Bs[s][br][b_c4 * 4]) = vb;
        }
    };

    prefetch(0);
    stage(0);
    __syncthreads();

    const int lg = lane >> 2;   // 0..7
    const int lk = lane & 3;    // 0..3

    for (int k0 = 0; k0 < K; k0 += 16) {
        int s = (k0 >> 4) & 1;
        bool more = (k0 + 16) < K;
        if (more) prefetch(k0 + 16);

#pragma unroll
        for (int ks = 0; ks < 2; ks++) {
            int kb = ks * 8;
            unsigned af[4][4], bf[4][2];
#pragma unroll
            for (int mi = 0; mi < 4; mi++) {
                int r = wm + mi * 16 + lg;
                af[mi][0] = __float_as_uint(As[s][r][kb + lk]);
                af[mi][1] = __float_as_uint(As[s][r + 8][kb + lk]);
                af[mi][2] = __float_as_uint(As[s][r][kb + lk + 4]);
                af[mi][3] = __float_as_uint(As[s][r + 8][kb + lk + 4]);
            }
#pragma unroll
            for (int ni = 0; ni < 4; ni++) {
                int cn = wn + ni * 8 + lg;
                bf[ni][0] = __float_as_uint(Bs[s][kb + lk][cn]);
                bf[ni][1] = __float_as_uint(Bs[s][kb + lk + 4][cn]);
            }
#pragma unroll
            for (int mi = 0; mi < 4; mi++)
#pragma unroll
                for (int ni = 0; ni < 4; ni++) {
                    asm volatile(
                        "mma.sync.aligned.m16n8k8.row.col.f32.tf32.tf32.f32 "
                        "{%0,%1,%2,%3}, {%4,%5,%6,%7}, {%8,%9}, {%0,%1,%2,%3};"
                        : "+f"(acc[mi][ni][0]), "+f"(acc[mi][ni][1]),
                          "+f"(acc[mi][ni][2]), "+f"(acc[mi][ni][3])
                        : "r"(af[mi][0]), "r"(af[mi][1]),
                          "r"(af[mi][2]), "r"(af[mi][3]),
                          "r"(bf[ni][0]), "r"(bf[ni][1]));
                }
        }

        if (more) {
            stage(s ^ 1);
        }
        __syncthreads();
    }

    // epilogue + bias. c0,c1: (row, col),(row,col+1); c2,c3: row+8
#pragma unroll
    for (int mi = 0; mi < 4; mi++) {
#pragma unroll
        for (int ni = 0; ni < 4; ni++) {
            int row = bm + wm + mi * 16 + lg;
            int col = bn + wn + ni * 8 + (lk << 1);
            float b0 = bias[col], b1 = bias[col + 1];
            float2 v0 = make_float2(acc[mi][ni][0] + b0, acc[mi][ni][1] + b1);
            float2 v1 = make_float2(acc[mi][ni][2] + b0, acc[mi][ni][3] + b1);
            *(float2*)(C + (size_t)row * N + col) = v0;
            *(float2*)(C + (size_t)(row + 8) * N + col) = v1;
        }
    }
}

// ---------------------------------------------------------------------------
// Causal flash attention, fp32. (unchanged except lazy max-rescale)
// grid = (T/128, B*H), block = 128 threads. One thread per query row.
// ---------------------------------------------------------------------------
__global__ __launch_bounds__(128) void attn_kernel(
    const float* __restrict__ qkv, float* __restrict__ y)
{
    const int qb = blockIdx.x;
    const int bh = blockIdx.y;
    const int b = bh >> 4;
    const int h = bh & 15;
    const int tid = threadIdx.x;
    const int qi = qb * 128 + tid;

    __shared__ float Ks[64][64];
    __shared__ float Vs[64][64];

    const float* base = qkv + (size_t)b * Tt * N3;

    float4 q[16];
    {
        const float4* qrow = (const float4*)(base + (size_t)qi * N3 + h * Dd);
#pragma unroll
        for (int i = 0; i < 16; i++) q[i] = qrow[i];
    }

    float4 acc[16];
#pragma unroll
    for (int i = 0; i < 16; i++) acc[i] = make_float4(0.f, 0.f, 0.f, 0.f);
    float m = -1e30f, l = 0.f;

    const int ntiles = 2 * qb + 2;
    const int lr = tid >> 4;
    const int lc = tid & 15;

#pragma unroll 1
    for (int kb = 0; kb < ntiles; kb++) {
        __syncthreads();
#pragma unroll
        for (int p = 0; p < 8; p++) {
            int r = lr + p * 8;
            const float* krow = base + (size_t)(kb * 64 + r) * N3 + Cc + h * Dd;
            ((float4*)Ks[r])[lc] = ((const float4*)krow)[lc];
            ((float4*)Vs[r])[lc] = ((const float4*)(krow + Cc))[lc];
        }
        __syncthreads();

#pragma unroll 1
        for (int jc = 0; jc < 64; jc += 8) {
            float s[8];
#pragma unroll
            for (int j = 0; j < 8; j++) {
                const float4* kr = (const float4*)Ks[jc + j];
                float ss = 0.f;
#pragma unroll
                for (int d = 0; d < 16; d++) {
                    float4 kk = kr[d];
                    ss += q[d].x * kk.x + q[d].y * kk.y
                        + q[d].z * kk.z + q[d].w * kk.w;
                }
                int kj = kb * 64 + jc + j;
                s[j] = (kj <= qi) ? ss * ATT_SCALE : -1e30f;
            }
            float mc = s[0];
#pragma unroll
            for (int j = 1; j < 8; j++) mc = fmaxf(mc, s[j]);
            if (mc > m) {              // lazy rescale: only when max moves
                float corr = __expf(m - mc);
                m = mc;
                l *= corr;
#pragma unroll
                for (int d = 0; d < 16; d++) {
                    acc[d].x *= corr; acc[d].y *= corr;
                    acc[d].z *= corr; acc[d].w *= corr;
                }
            }
#pragma unroll
            for (int j = 0; j < 8; j++) {
                float p = __expf(s[j] - m);
                l += p;
                const float4* vr = (const float4*)Vs[jc + j];
#pragma unroll
                for (int d = 0; d < 16; d++) {
                    float4 vv = vr[d];
                    acc[d].x += p * vv.x; acc[d].y += p * vv.y;
                    acc[d].z += p * vv.z; acc[d].w += p * vv.w;
                }
            }
        }
    }

    float inv = 1.f / l;
    float4* yrow = (float4*)(y + ((size_t)b * Tt + qi) * Cc + h * Dd);
#pragma unroll
    for (int d = 0; d < 16; d++) {
        float4 o = acc[d];
        o.x *= inv; o.y *= inv; o.z *= inv; o.w *= inv;
        yrow[d] = o;
    }
}

// ---------------------------------------------------------------------------
extern "C" void kernel_launch(void* const* d_in, const int* in_sizes, int n_in,
                              void* d_out, int out_size)
{
    const float* x      = (const float*)d_in[0];
    const float* w_attn = (const float*)d_in[1];
    const float* b_attn = (const float*)d_in[2];
    const float* w_proj = (const float*)d_in[3];
    const float* b_proj = (const float*)d_in[4];
    float* out = (float*)d_out;

    void* qkv_p = nullptr;
    void* y_p = nullptr;
    cudaGetSymbolAddress(&qkv_p, g_qkv);
    cudaGetSymbolAddress(&y_p, g_y);
    float* qkv = (float*)qkv_p;
    float* y   = (float*)y_p;

    // 1) qkv = x @ w_attn + b_attn    [4096,3072]
    {
        dim3 grid(N3 / 128, Mm / 128);
        gemm_tf32_bias_kernel<<<grid, 256>>>(x, w_attn, b_attn, qkv, Mm, N3, Cc);
    }
    // 2) causal attention -> y [4096,1024]
    {
        dim3 grid(Tt / 128, Bt * Hh);
        attn_kernel<<<grid, 128>>>(qkv, y);
    }
    // 3) out = y @ w_proj + b_proj   [4096,1024]
    {
        dim3 grid(Cc / 128, Mm / 128);
        gemm_tf32_bias_kernel<<<grid, 256>>>(y, w_proj, b_proj, out, Mm, Cc, Cc);
    }
}

// round 3
// speedup vs baseline: 3.0781x; 2.1413x over previous
#include <cuda_runtime.h>
#include <cuda_bf16.h>

// Problem constants
#define Bt 2
#define Tt 2048
#define Cc 1024
#define Hh 16
#define Dd 64
#define N3 (3 * Cc)          // 3072
#define Mm (Bt * Tt)         // 4096
#define ATT_SCALE (0.1f / 8.0f)   // 0.1 / sqrt(64)

// Scratch (allocation-free rule: __device__ globals)
__device__ float g_qkv[(size_t)Mm * N3];   // [4096, 3072]
__device__ float g_y[(size_t)Mm * Cc];     // [4096, 1024]

__device__ __forceinline__ unsigned f2tf32(float x) {
    unsigned r;
    asm("cvt.rna.tf32.f32 %0, %1;" : "=r"(r) : "f"(x));
    return r;
}

#define MMA_TF32(d, a, b0, b1)                                              \
    asm volatile(                                                           \
        "mma.sync.aligned.m16n8k8.row.col.f32.tf32.tf32.f32 "               \
        "{%0,%1,%2,%3}, {%4,%5,%6,%7}, {%8,%9}, {%0,%1,%2,%3};"             \
        : "+f"(d[0]), "+f"(d[1]), "+f"(d[2]), "+f"(d[3])                    \
        : "r"(a[0]), "r"(a[1]), "r"(a[2]), "r"(a[3]), "r"(b0), "r"(b1))

// ---------------------------------------------------------------------------
// TF32 tensor-core GEMM + bias: C[M,N] = A[M,K] @ B[K,N] + bias[N]
// (unchanged from round 2)
// ---------------------------------------------------------------------------
__global__ __launch_bounds__(256, 2) void gemm_tf32_bias_kernel(
    const float* __restrict__ A, const float* __restrict__ Bm,
    const float* __restrict__ bias, float* __restrict__ C,
    int M, int N, int K)
{
    __shared__ float As[2][128][20];
    __shared__ float Bs[2][16][132];

    const int tid  = threadIdx.x;
    const int lane = tid & 31;
    const int warp = tid >> 5;
    const int bm = blockIdx.y * 128;
    const int bn = blockIdx.x * 128;
    const int wm = (warp >> 2) * 64;
    const int wn = (warp & 3) * 32;

    float acc[4][4][4];
#pragma unroll
    for (int i = 0; i < 4; i++)
#pragma unroll
        for (int j = 0; j < 4; j++)
#pragma unroll
            for (int r = 0; r < 4; r++) acc[i][j][r] = 0.f;

    const int a_row0 = tid >> 2;
    const int a_c4   = (tid & 3);
    const int b_row0 = tid >> 5;
    const int b_c4   = (tid & 31);

    float4 pa[2], pb[2];

    auto prefetch = [&](int k0) {
#pragma unroll
        for (int i = 0; i < 2; i++) {
            int ar = a_row0 + i * 64;
            pa[i] = *(const float4*)(A + (size_t)(bm + ar) * K + k0 + a_c4 * 4);
            int br = b_row0 + i * 8;
            pb[i] = *(const float4*)(Bm + (size_t)(k0 + br) * N + bn + b_c4 * 4);
        }
    };
    auto stage = [&](int s) {
#pragma unroll
        for (int i = 0; i < 2; i++) {
            int ar = a_row0 + i * 64;
            float4 va;
            va.x = __uint_as_float(f2tf32(pa[i].x));
            va.y = __uint_as_float(f2tf32(pa[i].y));
            va.z = __uint_as_float(f2tf32(pa[i].z));
            va.w = __uint_as_float(f2tf32(pa[i].w));
            *(float4*)(&As[s][ar][a_c4 * 4]) = va;
            int br = b_row0 + i * 8;
            float4 vb;
            vb.x = __uint_as_float(f2tf32(pb[i].x));
            vb.y = __uint_as_float(f2tf32(pb[i].y));
            vb.z = __uint_as_float(f2tf32(pb[i].z));
            vb.w = __uint_as_float(f2tf32(pb[i].w));
            *(float4*)(&Bs[s][br][b_c4 * 4]) = vb;
        }
    };

    prefetch(0);
    stage(0);
    __syncthreads();

    const int lg = lane >> 2;
    const int lk = lane & 3;

    for (int k0 = 0; k0 < K; k0 += 16) {
        int s = (k0 >> 4) & 1;
        bool more = (k0 + 16) < K;
        if (more) prefetch(k0 + 16);

#pragma unroll
        for (int ks = 0; ks < 2; ks++) {
            int kb = ks * 8;
            unsigned af[4][4], bf[4][2];
#pragma unroll
            for (int mi = 0; mi < 4; mi++) {
                int r = wm + mi * 16 + lg;
                af[mi][0] = __float_as_uint(As[s][r][kb + lk]);
                af[mi][1] = __float_as_uint(As[s][r + 8][kb + lk]);
                af[mi][2] = __float_as_uint(As[s][r][kb + lk + 4]);
                af[mi][3] = __float_as_uint(As[s][r + 8][kb + lk + 4]);
            }
#pragma unroll
            for (int ni = 0; ni < 4; ni++) {
                int cn = wn + ni * 8 + lg;
                bf[ni][0] = __float_as_uint(Bs[s][kb + lk][cn]);
                bf[ni][1] = __float_as_uint(Bs[s][kb + lk + 4][cn]);
            }
#pragma unroll
            for (int mi = 0; mi < 4; mi++)
#pragma unroll
                for (int ni = 0; ni < 4; ni++)
                    MMA_TF32(acc[mi][ni], af[mi], bf[ni][0], bf[ni][1]);
        }

        if (more) stage(s ^ 1);
        __syncthreads();
    }

#pragma unroll
    for (int mi = 0; mi < 4; mi++) {
#pragma unroll
        for (int ni = 0; ni < 4; ni++) {
            int row = bm + wm + mi * 16 + lg;
            int col = bn + wn + ni * 8 + (lk << 1);
            float b0 = bias[col], b1 = bias[col + 1];
            float2 v0 = make_float2(acc[mi][ni][0] + b0, acc[mi][ni][1] + b1);
            float2 v1 = make_float2(acc[mi][ni][2] + b0, acc[mi][ni][3] + b1);
            *(float2*)(C + (size_t)row * N + col) = v0;
            *(float2*)(C + (size_t)(row + 8) * N + col) = v1;
        }
    }
}

// ---------------------------------------------------------------------------
// Tensor-core causal flash attention (tf32 mma).
// grid = (T/128, B*H), 256 threads = 8 warps, warp owns 16 q-rows.
// K/V tiles: 64 keys, natural [key][d] layout (strides 68 / 72 chosen so all
// mma fragment LDS are bank-conflict-free). P roundtrips via per-warp SMEM.
// ---------------------------------------------------------------------------
#define KS_STRIDE 68
#define VS_STRIDE 72
#define PS_STRIDE 68
#define SMEM_ATTN ((64 * KS_STRIDE + 64 * VS_STRIDE + 128 * PS_STRIDE) * 4)

__global__ __launch_bounds__(256, 2) void attn_tc_kernel(
    const float* __restrict__ qkv, float* __restrict__ y)
{
    extern __shared__ float sm[];
    float (*Ks)[KS_STRIDE] = (float(*)[KS_STRIDE])sm;
    float (*Vs)[VS_STRIDE] = (float(*)[VS_STRIDE])(sm + 64 * KS_STRIDE);
    float (*Ps)[PS_STRIDE] =
        (float(*)[PS_STRIDE])(sm + 64 * KS_STRIDE + 64 * VS_STRIDE);

    const int qb = (gridDim.x - 1) - blockIdx.x;   // heavy tiles first
    const int bh = blockIdx.y;
    const int b = bh >> 4;
    const int h = bh & 15;
    const int tid = threadIdx.x;
    const int lane = tid & 31;
    const int warp = tid >> 5;
    const int lg = lane >> 2;
    const int lk = lane & 3;
    const int wrow = warp * 16;

    const float* base  = qkv + (size_t)b * Tt * N3;
    const float* kbase = base + Cc + h * Dd;

    // Q fragments (scale folded in), loaded once.
    unsigned qf[8][4];
    {
        const float* q0 = base + (size_t)(qb * 128 + wrow + lg) * N3 + h * Dd;
        const float* q1 = q0 + 8 * (size_t)N3;
#pragma unroll
        for (int ks = 0; ks < 8; ks++) {
            qf[ks][0] = f2tf32(q0[ks * 8 + lk] * ATT_SCALE);
            qf[ks][1] = f2tf32(q1[ks * 8 + lk] * ATT_SCALE);
            qf[ks][2] = f2tf32(q0[ks * 8 + lk + 4] * ATT_SCALE);
            qf[ks][3] = f2tf32(q1[ks * 8 + lk + 4] * ATT_SCALE);
        }
    }

    float o[8][4];
#pragma unroll
    for (int nt = 0; nt < 8; nt++)
#pragma unroll
        for (int r = 0; r < 4; r++) o[nt][r] = 0.f;
    float m0 = -1e30f, m1 = -1e30f, l0 = 0.f, l1 = 0.f;

    const int ntiles = 2 * qb + 2;
    const int ldr = tid >> 2;     // 0..63
    const int ldc = tid & 3;      // float4 col base

    const int q0g = qb * 128 + wrow + lg;
    const int q1g = q0g + 8;

#pragma unroll 1
    for (int kb = 0; kb < ntiles; kb++) {
        __syncthreads();
        // cooperative K/V tile load, cvt to tf32 at store
#pragma unroll
        for (int i = 0; i < 4; i++) {
            int c4 = ldc + i * 4;
            const float* kr = kbase + (size_t)(kb * 64 + ldr) * N3 + c4 * 4;
            float4 kv = *(const float4*)kr;
            float4 vv = *(const float4*)(kr + Cc);
            float4 kc, vc;
            kc.x = __uint_as_float(f2tf32(kv.x));
            kc.y = __uint_as_float(f2tf32(kv.y));
            kc.z = __uint_as_float(f2tf32(kv.z));
            kc.w = __uint_as_float(f2tf32(kv.w));
            vc.x = __uint_as_float(f2tf32(vv.x));
            vc.y = __uint_as_float(f2tf32(vv.y));
            vc.z = __uint_as_float(f2tf32(vv.z));
            vc.w = __uint_as_float(f2tf32(vv.w));
            *(float4*)(&Ks[ldr][c4 * 4]) = kc;
            *(float4*)(&Vs[ldr][c4 * 4]) = vc;
        }
        __syncthreads();

        // ---- S = Q @ K^T (per-warp 16x64) ----
        float sa[8][4];
#pragma unroll
        for (int nt = 0; nt < 8; nt++)
#pragma unroll
            for (int r = 0; r < 4; r++) sa[nt][r] = 0.f;

#pragma unroll
        for (int ks = 0; ks < 8; ks++) {
#pragma unroll
            for (int nt = 0; nt < 8; nt++) {
                unsigned b0 = __float_as_uint(Ks[nt * 8 + lg][ks * 8 + lk]);
                unsigned b1 = __float_as_uint(Ks[nt * 8 + lg][ks * 8 + lk + 4]);
                MMA_TF32(sa[nt], qf[ks], b0, b1);
            }
        }

        // ---- causal mask (only for warps whose tile crosses the diagonal) ----
        if (kb * 64 + 63 > qb * 128 + wrow) {
#pragma unroll
            for (int nt = 0; nt < 8; nt++) {
                int kg = kb * 64 + nt * 8 + 2 * lk;
                sa[nt][0] = (kg     <= q0g) ? sa[nt][0] : -1e30f;
                sa[nt][1] = (kg + 1 <= q0g) ? sa[nt][1] : -1e30f;
                sa[nt][2] = (kg     <= q1g) ? sa[nt][2] : -1e30f;
                sa[nt][3] = (kg + 1 <= q1g) ? sa[nt][3] : -1e30f;
            }
        }

        // ---- online softmax ----
        float mt0 = -1e30f, mt1 = -1e30f;
#pragma unroll
        for (int nt = 0; nt < 8; nt++) {
            mt0 = fmaxf(mt0, fmaxf(sa[nt][0], sa[nt][1]));
            mt1 = fmaxf(mt1, fmaxf(sa[nt][2], sa[nt][3]));
        }
        mt0 = fmaxf(mt0, __shfl_xor_sync(0xffffffff, mt0, 1));
        mt0 = fmaxf(mt0, __shfl_xor_sync(0xffffffff, mt0, 2));
        mt1 = fmaxf(mt1, __shfl_xor_sync(0xffffffff, mt1, 1));
        mt1 = fmaxf(mt1, __shfl_xor_sync(0xffffffff, mt1, 2));

        float mn0 = fmaxf(m0, mt0), mn1 = fmaxf(m1, mt1);
        float sc0 = __expf(m0 - mn0), sc1 = __expf(m1 - mn1);
        m0 = mn0; m1 = mn1;

#pragma unroll
        for (int nt = 0; nt < 8; nt++) {
            o[nt][0] *= sc0; o[nt][1] *= sc0;
            o[nt][2] *= sc1; o[nt][3] *= sc1;
        }

        float s0 = 0.f, s1 = 0.f;
#pragma unroll
        for (int nt = 0; nt < 8; nt++) {
            float p0 = __expf(sa[nt][0] - mn0);
            float p1 = __expf(sa[nt][1] - mn0);
            float p2 = __expf(sa[nt][2] - mn1);
            float p3 = __expf(sa[nt][3] - mn1);
            s0 += p0 + p1; s1 += p2 + p3;
            float2 v0, v1;
            v0.x = __uint_as_float(f2tf32(p0));
            v0.y = __uint_as_float(f2tf32(p1));
            v1.x = __uint_as_float(f2tf32(p2));
            v1.y = __uint_as_float(f2tf32(p3));
            *(float2*)(&Ps[wrow + lg][nt * 8 + 2 * lk]) = v0;
            *(float2*)(&Ps[wrow + 8 + lg][nt * 8 + 2 * lk]) = v1;
        }
        s0 += __shfl_xor_sync(0xffffffff, s0, 1);
        s0 += __shfl_xor_sync(0xffffffff, s0, 2);
        s1 += __shfl_xor_sync(0xffffffff, s1, 1);
        s1 += __shfl_xor_sync(0xffffffff, s1, 2);
        l0 = l0 * sc0 + s0;
        l1 = l1 * sc1 + s1;

        __syncwarp();

        // ---- O += P @ V ----
#pragma unroll
        for (int ks = 0; ks < 8; ks++) {
            unsigned af[4];
            af[0] = __float_as_uint(Ps[wrow + lg][ks * 8 + lk]);
            af[1] = __float_as_uint(Ps[wrow + 8 + lg][ks * 8 + lk]);
            af[2] = __float_as_uint(Ps[wrow + lg][ks * 8 + lk + 4]);
            af[3] = __float_as_uint(Ps[wrow + 8 + lg][ks * 8 + lk + 4]);
#pragma unroll
            for (int nt = 0; nt < 8; nt++) {
                unsigned b0 = __float_as_uint(Vs[ks * 8 + lk][nt * 8 + lg]);
                unsigned b1 = __float_as_uint(Vs[ks * 8 + lk + 4][nt * 8 + lg]);
                MMA_TF32(o[nt], af, b0, b1);
            }
        }
    }

    // ---- epilogue ----
    float i0 = 1.f / l0, i1 = 1.f / l1;
    float* y0 = y + ((size_t)b * Tt + qb * 128 + wrow + lg) * Cc + h * Dd;
    float* y1 = y0 + 8 * (size_t)Cc;
#pragma unroll
    for (int nt = 0; nt < 8; nt++) {
        *(float2*)(y0 + nt * 8 + 2 * lk) =
            make_float2(o[nt][0] * i0, o[nt][1] * i0);
        *(float2*)(y1 + nt * 8 + 2 * lk) =
            make_float2(o[nt][2] * i1, o[nt][3] * i1);
    }
}

// ---------------------------------------------------------------------------
extern "C" void kernel_launch(void* const* d_in, const int* in_sizes, int n_in,
                              void* d_out, int out_size)
{
    const float* x      = (const float*)d_in[0];
    const float* w_attn = (const float*)d_in[1];
    const float* b_attn = (const float*)d_in[2];
    const float* w_proj = (const float*)d_in[3];
    const float* b_proj = (const float*)d_in[4];
    float* out = (float*)d_out;

    void* qkv_p = nullptr;
    void* y_p = nullptr;
    cudaGetSymbolAddress(&qkv_p, g_qkv);
    cudaGetSymbolAddress(&y_p, g_y);
    float* qkv = (float*)qkv_p;
    float* y   = (float*)y_p;

    cudaFuncSetAttribute(attn_tc_kernel,
                         cudaFuncAttributeMaxDynamicSharedMemorySize,
                         SMEM_ATTN);

    // 1) qkv = x @ w_attn + b_attn    [4096,3072]
    {
        dim3 grid(N3 / 128, Mm / 128);
        gemm_tf32_bias_kernel<<<grid, 256>>>(x, w_attn, b_attn, qkv, Mm, N3, Cc);
    }
    // 2) causal attention -> y [4096,1024]
    {
        dim3 grid(Tt / 128, Bt * Hh);
        attn_tc_kernel<<<grid, 256, SMEM_ATTN>>>(qkv, y);
    }
    // 3) out = y @ w_proj + b_proj   [4096,1024]
    {
        dim3 grid(Cc / 128, Mm / 128);
        gemm_tf32_bias_kernel<<<grid, 256>>>(y, w_proj, b_proj, out, Mm, Cc, Cc);
    }
}

// round 4
// speedup vs baseline: 3.1620x; 1.0272x over previous
#include <cuda_runtime.h>
#include <cuda_bf16.h>
#include <cstdint>

// Problem constants
#define Bt 2
#define Tt 2048
#define Cc 1024
#define Hh 16
#define Dd 64
#define N3 (3 * Cc)          // 3072
#define Mm (Bt * Tt)         // 4096
#define ATT_SCALE (0.1f / 8.0f)   // 0.1 / sqrt(64)

// Scratch (allocation-free rule: __device__ globals)
__device__ float g_qkv[(size_t)Mm * N3];   // [4096, 3072] (tf32-rounded)
__device__ float g_y[(size_t)Mm * Cc];     // [4096, 1024] (tf32-rounded)
__device__ float g_xr[(size_t)Mm * Cc];    // x, tf32-rounded
__device__ float g_war[(size_t)Cc * N3];   // w_attn, tf32-rounded
__device__ float g_wpr[(size_t)Cc * Cc];   // w_proj, tf32-rounded

__device__ __forceinline__ unsigned f2tf32(float x) {
    unsigned r;
    asm("cvt.rna.tf32.f32 %0, %1;" : "=r"(r) : "f"(x));
    return r;
}

#define MMA_TF32(d, a, b0, b1)                                              \
    asm volatile(                                                           \
        "mma.sync.aligned.m16n8k8.row.col.f32.tf32.tf32.f32 "               \
        "{%0,%1,%2,%3}, {%4,%5,%6,%7}, {%8,%9}, {%0,%1,%2,%3};"             \
        : "+f"(d[0]), "+f"(d[1]), "+f"(d[2]), "+f"(d[3])                    \
        : "r"(a[0]), "r"(a[1]), "r"(a[2]), "r"(a[3]), "r"(b0), "r"(b1))

__device__ __forceinline__ void cp16(uint32_t s, const void* g) {
    asm volatile("cp.async.cg.shared.global [%0], [%1], 16;"
                 :: "r"(s), "l"(g));
}

// ---------------------------------------------------------------------------
// Elementwise tf32 rounding (float4 grid-stride)
// ---------------------------------------------------------------------------
__global__ void cvt_tf32_kernel(const float* __restrict__ in,
                                float* __restrict__ out, int n4)
{
    for (int i = blockIdx.x * blockDim.x + threadIdx.x; i < n4;
         i += gridDim.x * blockDim.x) {
        float4 v = ((const float4*)in)[i];
        v.x = __uint_as_float(f2tf32(v.x));
        v.y = __uint_as_float(f2tf32(v.y));
        v.z = __uint_as_float(f2tf32(v.z));
        v.w = __uint_as_float(f2tf32(v.w));
        ((float4*)out)[i] = v;
    }
}

// ---------------------------------------------------------------------------
// TF32 tensor-core GEMM + bias, cp.async 3-stage pipeline.
// Inputs must already be tf32-valued fp32. round_out: round result to tf32.
// CTA tile 128x128, BK=16, 8 warps (2x4), warp tile 64x32, m16n8k8.
// ---------------------------------------------------------------------------
#define GSTAGE 3
#define A_ST 20
#define B_ST 132
#define SMEM_GEMM (GSTAGE * (128 * A_ST + 16 * B_ST) * 4)

__global__ __launch_bounds__(256, 2) void gemm_tf32_bias_kernel(
    const float* __restrict__ A, const float* __restrict__ Bm,
    const float* __restrict__ bias, float* __restrict__ C,
    int M, int N, int K, int round_out)
{
    extern __shared__ float sm[];
    float (*As)[128][A_ST] = (float(*)[128][A_ST])sm;
    float (*Bs)[16][B_ST]  = (float(*)[16][B_ST])(sm + GSTAGE * 128 * A_ST);

    const int tid  = threadIdx.x;
    const int lane = tid & 31;
    const int warp = tid >> 5;
    const int bm = blockIdx.y * 128;
    const int bn = blockIdx.x * 128;
    const int wm = (warp >> 2) * 64;
    const int wn = (warp & 3) * 32;

    float acc[4][4][4];
#pragma unroll
    for (int i = 0; i < 4; i++)
#pragma unroll
        for (int j = 0; j < 4; j++)
#pragma unroll
            for (int r = 0; r < 4; r++) acc[i][j][r] = 0.f;

    const int a_row0 = tid >> 2;
    const int a_c4   = (tid & 3) * 4;
    const int b_row0 = tid >> 5;
    const int b_c4   = (tid & 31) * 4;

    const int KT = K >> 4;

    auto issue = [&](int kt) {
        int s = kt % GSTAGE;
        int k0 = kt << 4;
#pragma unroll
        for (int i = 0; i < 2; i++) {
            int ar = a_row0 + i * 64;
            cp16((uint32_t)__cvta_generic_to_shared(&As[s][ar][a_c4]),
                 A + (size_t)(bm + ar) * K + k0 + a_c4);
            int br = b_row0 + i * 8;
            cp16((uint32_t)__cvta_generic_to_shared(&Bs[s][br][b_c4]),
                 Bm + (size_t)(k0 + br) * N + bn + b_c4);
        }
        asm volatile("cp.async.commit_group;" ::: "memory");
    };

    issue(0);
    issue(1);

    const int lg = lane >> 2;
    const int lk = lane & 3;

    for (int kt = 0; kt < KT; kt++) {
        if (kt + 1 < KT)
            asm volatile("cp.async.wait_group 1;" ::: "memory");
        else
            asm volatile("cp.async.wait_group 0;" ::: "memory");
        __syncthreads();
        if (kt + 2 < KT) issue(kt + 2);

        int s = kt % GSTAGE;
        float (*Asb)[A_ST] = As[s];
        float (*Bsb)[B_ST] = Bs[s];

#pragma unroll
        for (int ks = 0; ks < 2; ks++) {
            int kb = ks * 8;
            unsigned af[4][4], bf[4][2];
#pragma unroll
            for (int mi = 0; mi < 4; mi++) {
                int r = wm + mi * 16 + lg;
                af[mi][0] = __float_as_uint(Asb[r][kb + lk]);
                af[mi][1] = __float_as_uint(Asb[r + 8][kb + lk]);
                af[mi][2] = __float_as_uint(Asb[r][kb + lk + 4]);
                af[mi][3] = __float_as_uint(Asb[r + 8][kb + lk + 4]);
            }
#pragma unroll
            for (int ni = 0; ni < 4; ni++) {
                int cn = wn + ni * 8 + lg;
                bf[ni][0] = __float_as_uint(Bsb[kb + lk][cn]);
                bf[ni][1] = __float_as_uint(Bsb[kb + lk + 4][cn]);
            }
#pragma unroll
            for (int mi = 0; mi < 4; mi++)
#pragma unroll
                for (int ni = 0; ni < 4; ni++)
                    MMA_TF32(acc[mi][ni], af[mi], bf[ni][0], bf[ni][1]);
        }
        __syncthreads();
    }

#pragma unroll
    for (int mi = 0; mi < 4; mi++) {
#pragma unroll
        for (int ni = 0; ni < 4; ni++) {
            int row = bm + wm + mi * 16 + lg;
            int col = bn + wn + ni * 8 + (lk << 1);
            float b0 = bias[col], b1 = bias[col + 1];
            float2 v0 = make_float2(acc[mi][ni][0] + b0, acc[mi][ni][1] + b1);
            float2 v1 = make_float2(acc[mi][ni][2] + b0, acc[mi][ni][3] + b1);
            if (round_out) {
                v0.x = __uint_as_float(f2tf32(v0.x));
                v0.y = __uint_as_float(f2tf32(v0.y));
                v1.x = __uint_as_float(f2tf32(v1.x));
                v1.y = __uint_as_float(f2tf32(v1.y));
            }
            *(float2*)(C + (size_t)row * N + col) = v0;
            *(float2*)(C + (size_t)(row + 8) * N + col) = v1;
        }
    }
}

// ---------------------------------------------------------------------------
// Tensor-core causal flash attention (tf32 mma). qkv pre-rounded to tf32.
// ---------------------------------------------------------------------------
#define KS_STRIDE 68
#define VS_STRIDE 72
#define PS_STRIDE 68
#define SMEM_ATTN ((64 * KS_STRIDE + 64 * VS_STRIDE + 128 * PS_STRIDE) * 4)

__global__ __launch_bounds__(256, 2) void attn_tc_kernel(
    const float* __restrict__ qkv, float* __restrict__ y)
{
    extern __shared__ float sm[];
    float (*Ks)[KS_STRIDE] = (float(*)[KS_STRIDE])sm;
    float (*Vs)[VS_STRIDE] = (float(*)[VS_STRIDE])(sm + 64 * KS_STRIDE);
    float (*Ps)[PS_STRIDE] =
        (float(*)[PS_STRIDE])(sm + 64 * KS_STRIDE + 64 * VS_STRIDE);

    const int qb = (gridDim.x - 1) - blockIdx.x;
    const int bh = blockIdx.y;
    const int b = bh >> 4;
    const int h = bh & 15;
    const int tid = threadIdx.x;
    const int lane = tid & 31;
    const int warp = tid >> 5;
    const int lg = lane >> 2;
    const int lk = lane & 3;
    const int wrow = warp * 16;

    const float* base  = qkv + (size_t)b * Tt * N3;
    const float* kbase = base + Cc + h * Dd;

    // Q fragments (scale folded; input already tf32-valued, rescale + rna).
    unsigned qf[8][4];
    {
        const float* q0 = base + (size_t)(qb * 128 + wrow + lg) * N3 + h * Dd;
        const float* q1 = q0 + 8 * (size_t)N3;
#pragma unroll
        for (int ks = 0; ks < 8; ks++) {
            qf[ks][0] = f2tf32(q0[ks * 8 + lk] * ATT_SCALE);
            qf[ks][1] = f2tf32(q1[ks * 8 + lk] * ATT_SCALE);
            qf[ks][2] = f2tf32(q0[ks * 8 + lk + 4] * ATT_SCALE);
            qf[ks][3] = f2tf32(q1[ks * 8 + lk + 4] * ATT_SCALE);
        }
    }

    float o[8][4];
#pragma unroll
    for (int nt = 0; nt < 8; nt++)
#pragma unroll
        for (int r = 0; r < 4; r++) o[nt][r] = 0.f;
    float m0 = -1e30f, m1 = -1e30f, l0 = 0.f, l1 = 0.f;

    const int ntiles = 2 * qb + 2;
    const int ldr = tid >> 2;
    const int ldc = tid & 3;

    const int q0g = qb * 128 + wrow + lg;
    const int q1g = q0g + 8;

#pragma unroll 1
    for (int kb = 0; kb < ntiles; kb++) {
        __syncthreads();
        // K/V tile load (already tf32-valued, plain copy)
#pragma unroll
        for (int i = 0; i < 4; i++) {
            int c4 = ldc + i * 4;
            const float* kr = kbase + (size_t)(kb * 64 + ldr) * N3 + c4 * 4;
            *(float4*)(&Ks[ldr][c4 * 4]) = *(const float4*)kr;
            *(float4*)(&Vs[ldr][c4 * 4]) = *(const float4*)(kr + Cc);
        }
        __syncthreads();

        // ---- S = Q @ K^T ----
        float sa[8][4];
#pragma unroll
        for (int nt = 0; nt < 8; nt++)
#pragma unroll
            for (int r = 0; r < 4; r++) sa[nt][r] = 0.f;

#pragma unroll
        for (int ks = 0; ks < 8; ks++) {
#pragma unroll
            for (int nt = 0; nt < 8; nt++) {
                unsigned b0 = __float_as_uint(Ks[nt * 8 + lg][ks * 8 + lk]);
                unsigned b1 = __float_as_uint(Ks[nt * 8 + lg][ks * 8 + lk + 4]);
                MMA_TF32(sa[nt], qf[ks], b0, b1);
            }
        }

        // ---- causal mask ----
        if (kb * 64 + 63 > qb * 128 + wrow) {
#pragma unroll
            for (int nt = 0; nt < 8; nt++) {
                int kg = kb * 64 + nt * 8 + 2 * lk;
                sa[nt][0] = (kg     <= q0g) ? sa[nt][0] : -1e30f;
                sa[nt][1] = (kg + 1 <= q0g) ? sa[nt][1] : -1e30f;
                sa[nt][2] = (kg     <= q1g) ? sa[nt][2] : -1e30f;
                sa[nt][3] = (kg + 1 <= q1g) ? sa[nt][3] : -1e30f;
            }
        }

        // ---- online softmax ----
        float mt0 = -1e30f, mt1 = -1e30f;
#pragma unroll
        for (int nt = 0; nt < 8; nt++) {
            mt0 = fmaxf(mt0, fmaxf(sa[nt][0], sa[nt][1]));
            mt1 = fmaxf(mt1, fmaxf(sa[nt][2], sa[nt][3]));
        }
        mt0 = fmaxf(mt0, __shfl_xor_sync(0xffffffff, mt0, 1));
        mt0 = fmaxf(mt0, __shfl_xor_sync(0xffffffff, mt0, 2));
        mt1 = fmaxf(mt1, __shfl_xor_sync(0xffffffff, mt1, 1));
        mt1 = fmaxf(mt1, __shfl_xor_sync(0xffffffff, mt1, 2));

        float mn0 = fmaxf(m0, mt0), mn1 = fmaxf(m1, mt1);
        float sc0 = __expf(m0 - mn0), sc1 = __expf(m1 - mn1);
        m0 = mn0; m1 = mn1;

#pragma unroll
        for (int nt = 0; nt < 8; nt++) {
            o[nt][0] *= sc0; o[nt][1] *= sc0;
            o[nt][2] *= sc1; o[nt][3] *= sc1;
        }

        float s0 = 0.f, s1 = 0.f;
#pragma unroll
        for (int nt = 0; nt < 8; nt++) {
            float p0 = __expf(sa[nt][0] - mn0);
            float p1 = __expf(sa[nt][1] - mn0);
            float p2 = __expf(sa[nt][2] - mn1);
            float p3 = __expf(sa[nt][3] - mn1);
            s0 += p0 + p1; s1 += p2 + p3;
            float2 v0, v1;
            v0.x = __uint_as_float(f2tf32(p0));
            v0.y = __uint_as_float(f2tf32(p1));
            v1.x = __uint_as_float(f2tf32(p2));
            v1.y = __uint_as_float(f2tf32(p3));
            *(float2*)(&Ps[wrow + lg][nt * 8 + 2 * lk]) = v0;
            *(float2*)(&Ps[wrow + 8 + lg][nt * 8 + 2 * lk]) = v1;
        }
        s0 += __shfl_xor_sync(0xffffffff, s0, 1);
        s0 += __shfl_xor_sync(0xffffffff, s0, 2);
        s1 += __shfl_xor_sync(0xffffffff, s1, 1);
        s1 += __shfl_xor_sync(0xffffffff, s1, 2);
        l0 = l0 * sc0 + s0;
        l1 = l1 * sc1 + s1;

        __syncwarp();

        // ---- O += P @ V ----
#pragma unroll
        for (int ks = 0; ks < 8; ks++) {
            unsigned af[4];
            af[0] = __float_as_uint(Ps[wrow + lg][ks * 8 + lk]);
            af[1] = __float_as_uint(Ps[wrow + 8 + lg][ks * 8 + lk]);
            af[2] = __float_as_uint(Ps[wrow + lg][ks * 8 + lk + 4]);
            af[3] = __float_as_uint(Ps[wrow + 8 + lg][ks * 8 + lk + 4]);
#pragma unroll
            for (int nt = 0; nt < 8; nt++) {
                unsigned b0 = __float_as_uint(Vs[ks * 8 + lk][nt * 8 + lg]);
                unsigned b1 = __float_as_uint(Vs[ks * 8 + lk + 4][nt * 8 + lg]);
                MMA_TF32(o[nt], af, b0, b1);
            }
        }
    }

    // ---- epilogue (round y to tf32 for the projection GEMM) ----
    float i0 = 1.f / l0, i1 = 1.f / l1;
    float* y0 = y + ((size_t)b * Tt + qb * 128 + wrow + lg) * Cc + h * Dd;
    float* y1 = y0 + 8 * (size_t)Cc;
#pragma unroll
    for (int nt = 0; nt < 8; nt++) {
        float2 w0, w1;
        w0.x = __uint_as_float(f2tf32(o[nt][0] * i0));
        w0.y = __uint_as_float(f2tf32(o[nt][1] * i0));
        w1.x = __uint_as_float(f2tf32(o[nt][2] * i1));
        w1.y = __uint_as_float(f2tf32(o[nt][3] * i1));
        *(float2*)(y0 + nt * 8 + 2 * lk) = w0;
        *(float2*)(y1 + nt * 8 + 2 * lk) = w1;
    }
}

// ---------------------------------------------------------------------------
extern "C" void kernel_launch(void* const* d_in, const int* in_sizes, int n_in,
                              void* d_out, int out_size)
{
    const float* x      = (const float*)d_in[0];
    const float* w_attn = (const float*)d_in[1];
    const float* b_attn = (const float*)d_in[2];
    const float* w_proj = (const float*)d_in[3];
    const float* b_proj = (const float*)d_in[4];
    float* out = (float*)d_out;

    void *qkv_p, *y_p, *xr_p, *war_p, *wpr_p;
    cudaGetSymbolAddress(&qkv_p, g_qkv);
    cudaGetSymbolAddress(&y_p, g_y);
    cudaGetSymbolAddress(&xr_p, g_xr);
    cudaGetSymbolAddress(&war_p, g_war);
    cudaGetSymbolAddress(&wpr_p, g_wpr);
    float* qkv = (float*)qkv_p;
    float* y   = (float*)y_p;
    float* xr  = (float*)xr_p;
    float* war = (float*)war_p;
    float* wpr = (float*)wpr_p;

    static bool attr_set = false;
    if (!attr_set) {
        cudaFuncSetAttribute(attn_tc_kernel,
                             cudaFuncAttributeMaxDynamicSharedMemorySize,
                             SMEM_ATTN);
        cudaFuncSetAttribute(gemm_tf32_bias_kernel,
                             cudaFuncAttributeMaxDynamicSharedMemorySize,
                             SMEM_GEMM);
        attr_set = true;
    }

    // 0) pre-round GEMM inputs to tf32
    cvt_tf32_kernel<<<1024, 256>>>(x, xr, Mm * Cc / 4);
    cvt_tf32_kernel<<<1024, 256>>>(w_attn, war, Cc * N3 / 4);
    cvt_tf32_kernel<<<1024, 256>>>(w_proj, wpr, Cc * Cc / 4);

    // 1) qkv = xr @ war + b_attn  (output rounded to tf32)
    {
        dim3 grid(N3 / 128, Mm / 128);
        gemm_tf32_bias_kernel<<<grid, 256, SMEM_GEMM>>>(
            xr, war, b_attn, qkv, Mm, N3, Cc, 1);
    }
    // 2) causal attention -> y (rounded to tf32)
    {
        dim3 grid(Tt / 128, Bt * Hh);
        attn_tc_kernel<<<grid, 256, SMEM_ATTN>>>(qkv, y);
    }
    // 3) out = y @ wpr + b_proj  (full fp32 output)
    {
        dim3 grid(Cc / 128, Mm / 128);
        gemm_tf32_bias_kernel<<<grid, 256, SMEM_GEMM>>>(
            y, wpr, b_proj, out, Mm, Cc, Cc, 0);
    }
}

// round 6
// speedup vs baseline: 3.8679x; 1.2233x over previous
#include <cuda_runtime.h>
#include <cuda_bf16.h>
#include <cstdint>

// Problem constants
#define Bt 2
#define Tt 2048
#define Cc 1024
#define Hh 16
#define Dd 64
#define N3 (3 * Cc)          // 3072
#define Mm (Bt * Tt)         // 4096
#define ATT_SCALE (0.1f / 8.0f)   // 0.1 / sqrt(64)

// Scratch (allocation-free rule: __device__ globals)
__device__ float g_qkv[(size_t)Mm * N3];   // [4096, 3072] (tf32-rounded)
__device__ float g_y[(size_t)Mm * Cc];     // [4096, 1024] (tf32-rounded)
__device__ float g_xr[(size_t)Mm * Cc];    // x, tf32-rounded
__device__ float g_war[(size_t)Cc * N3];   // w_attn, tf32-rounded
__device__ float g_wpr[(size_t)Cc * Cc];   // w_proj, tf32-rounded

__device__ __forceinline__ unsigned f2tf32(float x) {
    unsigned r;
    asm("cvt.rna.tf32.f32 %0, %1;" : "=r"(r) : "f"(x));
    return r;
}

#define MMA_TF32(d, a, b0, b1)                                              \
    asm volatile(                                                           \
        "mma.sync.aligned.m16n8k8.row.col.f32.tf32.tf32.f32 "               \
        "{%0,%1,%2,%3}, {%4,%5,%6,%7}, {%8,%9}, {%0,%1,%2,%3};"             \
        : "+f"(d[0]), "+f"(d[1]), "+f"(d[2]), "+f"(d[3])                    \
        : "r"(a[0]), "r"(a[1]), "r"(a[2]), "r"(a[3]), "r"(b0), "r"(b1))

__device__ __forceinline__ void cp16(uint32_t s, const void* g) {
    asm volatile("cp.async.cg.shared.global [%0], [%1], 16;"
                 :: "r"(s), "l"(g));
}
#define CP_COMMIT() asm volatile("cp.async.commit_group;" ::: "memory")
#define CP_WAIT(n)  asm volatile("cp.async.wait_group %0;" :: "n"(n) : "memory")

// ---------------------------------------------------------------------------
// Elementwise tf32 rounding (float4 grid-stride)
// ---------------------------------------------------------------------------
__global__ void cvt_tf32_kernel(const float* __restrict__ in,
                                float* __restrict__ out, int n4)
{
    for (int i = blockIdx.x * blockDim.x + threadIdx.x; i < n4;
         i += gridDim.x * blockDim.x) {
        float4 v = ((const float4*)in)[i];
        v.x = __uint_as_float(f2tf32(v.x));
        v.y = __uint_as_float(f2tf32(v.y));
        v.z = __uint_as_float(f2tf32(v.z));
        v.w = __uint_as_float(f2tf32(v.w));
        ((float4*)out)[i] = v;
    }
}

// ---------------------------------------------------------------------------
// TF32 tensor-core GEMM + bias, cp.async 3-stage pipeline, BK=32.
// Inputs must already be tf32-valued fp32. round_out: round result to tf32.
// CTA tile 128x128, 8 warps (2x4), warp tile 64x32, m16n8k8.
// A stride 36 -> A-frag banks 4*lg+lk (conflict-free).
// B stride 136 -> B-frag banks 8*lk+lg (conflict-free).
// One __syncthreads per BK=32 iteration.
// ---------------------------------------------------------------------------
#define GSTAGE 3
#define A_ST 36
#define B_ST 136
#define SMEM_GEMM (GSTAGE * (128 * A_ST + 32 * B_ST) * 4)

__global__ __launch_bounds__(256, 2) void gemm_tf32_bias_kernel(
    const float* __restrict__ A, const float* __restrict__ Bm,
    const float* __restrict__ bias, float* __restrict__ C,
    int M, int N, int K, int round_out)
{
    extern __shared__ float sm[];
    float (*As)[128][A_ST] = (float(*)[128][A_ST])sm;
    float (*Bs)[32][B_ST]  = (float(*)[32][B_ST])(sm + GSTAGE * 128 * A_ST);

    const int tid  = threadIdx.x;
    const int lane = tid & 31;
    const int warp = tid >> 5;
    const int bm = blockIdx.y * 128;
    const int bn = blockIdx.x * 128;
    const int wm = (warp >> 2) * 64;
    const int wn = (warp & 3) * 32;

    float acc[4][4][4];
#pragma unroll
    for (int i = 0; i < 4; i++)
#pragma unroll
        for (int j = 0; j < 4; j++)
#pragma unroll
            for (int r = 0; r < 4; r++) acc[i][j][r] = 0.f;

    // cp.async indexing: A tile 128x32 (4 chunks), B tile 32x128 (4 chunks)
    const int a_row = tid >> 3;           // 0..31  (+ i*32)
    const int a_c   = (tid & 7) * 4;      // float col 0..28
    const int b_row = tid >> 5;           // 0..7   (+ i*8)
    const int b_c   = (tid & 31) * 4;     // float col 0..124

    const int KT = K >> 5;

    auto issue = [&](int kt) {
        int s = kt % GSTAGE;
        int k0 = kt << 5;
#pragma unroll
        for (int i = 0; i < 4; i++) {
            int ar = a_row + i * 32;
            cp16((uint32_t)__cvta_generic_to_shared(&As[s][ar][a_c]),
                 A + (size_t)(bm + ar) * K + k0 + a_c);
            int br = b_row + i * 8;
            cp16((uint32_t)__cvta_generic_to_shared(&Bs[s][br][b_c]),
                 Bm + (size_t)(k0 + br) * N + bn + b_c);
        }
        CP_COMMIT();
    };

    issue(0);
    issue(1);

    const int lg = lane >> 2;
    const int lk = lane & 3;

    for (int kt = 0; kt < KT; kt++) {
        if (kt + 1 < KT) { CP_WAIT(1); } else { CP_WAIT(0); }
        __syncthreads();
        if (kt + 2 < KT) issue(kt + 2);

        int s = kt % GSTAGE;
        float (*Asb)[A_ST] = As[s];
        float (*Bsb)[B_ST] = Bs[s];

#pragma unroll
        for (int ks = 0; ks < 4; ks++) {
            int kb = ks * 8;
            unsigned af[4][4], bf[4][2];
#pragma unroll
            for (int mi = 0; mi < 4; mi++) {
                int r = wm + mi * 16 + lg;
                af[mi][0] = __float_as_uint(Asb[r][kb + lk]);
                af[mi][1] = __float_as_uint(Asb[r + 8][kb + lk]);
                af[mi][2] = __float_as_uint(Asb[r][kb + lk + 4]);
                af[mi][3] = __float_as_uint(Asb[r + 8][kb + lk + 4]);
            }
#pragma unroll
            for (int ni = 0; ni < 4; ni++) {
                int cn = wn + ni * 8 + lg;
                bf[ni][0] = __float_as_uint(Bsb[kb + lk][cn]);
                bf[ni][1] = __float_as_uint(Bsb[kb + lk + 4][cn]);
            }
#pragma unroll
            for (int mi = 0; mi < 4; mi++)
#pragma unroll
                for (int ni = 0; ni < 4; ni++)
                    MMA_TF32(acc[mi][ni], af[mi], bf[ni][0], bf[ni][1]);
        }
    }

#pragma unroll
    for (int mi = 0; mi < 4; mi++) {
#pragma unroll
        for (int ni = 0; ni < 4; ni++) {
            int row = bm + wm + mi * 16 + lg;
            int col = bn + wn + ni * 8 + (lk << 1);
            float b0 = bias[col], b1 = bias[col + 1];
            float2 v0 = make_float2(acc[mi][ni][0] + b0, acc[mi][ni][1] + b1);
            float2 v1 = make_float2(acc[mi][ni][2] + b0, acc[mi][ni][3] + b1);
            if (round_out) {
                v0.x = __uint_as_float(f2tf32(v0.x));
                v0.y = __uint_as_float(f2tf32(v0.y));
                v1.x = __uint_as_float(f2tf32(v1.x));
                v1.y = __uint_as_float(f2tf32(v1.y));
            }
            *(float2*)(C + (size_t)row * N + col) = v0;
            *(float2*)(C + (size_t)(row + 8) * N + col) = v1;
        }
    }
}

// ---------------------------------------------------------------------------
// Tensor-core causal flash attention (tf32 mma), cp.async double-buffered K/V.
// qkv pre-rounded to tf32. One __syncthreads per key tile.
// ---------------------------------------------------------------------------
#define KS_STRIDE 68
#define VS_STRIDE 72
#define PS_STRIDE 68
#define SMEM_ATTN ((2 * 64 * (KS_STRIDE + VS_STRIDE) + 128 * PS_STRIDE) * 4)

__global__ __launch_bounds__(256, 2) void attn_tc_kernel(
    const float* __restrict__ qkv, float* __restrict__ y)
{
    extern __shared__ float sm[];
    float (*Ks)[64][KS_STRIDE] = (float(*)[64][KS_STRIDE])sm;
    float (*Vs)[64][VS_STRIDE] =
        (float(*)[64][VS_STRIDE])(sm + 2 * 64 * KS_STRIDE);
    float (*Ps)[PS_STRIDE] =
        (float(*)[PS_STRIDE])(sm + 2 * 64 * (KS_STRIDE + VS_STRIDE));

    const int qb = (gridDim.x - 1) - blockIdx.x;   // heavy tiles first
    const int bh = blockIdx.y;
    const int b = bh >> 4;
    const int h = bh & 15;
    const int tid = threadIdx.x;
    const int lane = tid & 31;
    const int warp = tid >> 5;
    const int lg = lane >> 2;
    const int lk = lane & 3;
    const int wrow = warp * 16;

    const float* base  = qkv + (size_t)b * Tt * N3;
    const float* kbase = base + Cc + h * Dd;

    const int ldr = tid >> 2;          // 0..63
    const int ldc = (tid & 3) * 4;     // float col base 0,4,8,12

    auto issue = [&](int kb) {
        int buf = kb & 1;
#pragma unroll
        for (int i = 0; i < 4; i++) {
            int c = ldc + i * 16;      // float col 0..60 (fixed: no extra *4)
            const float* kr = kbase + (size_t)(kb * 64 + ldr) * N3 + c;
            cp16((uint32_t)__cvta_generic_to_shared(&Ks[buf][ldr][c]), kr);
            cp16((uint32_t)__cvta_generic_to_shared(&Vs[buf][ldr][c]), kr + Cc);
        }
        CP_COMMIT();
    };

    issue(0);

    // Q fragments (scale folded; input already tf32-valued, rescale + rna).
    unsigned qf[8][4];
    {
        const float* q0 = base + (size_t)(qb * 128 + wrow + lg) * N3 + h * Dd;
        const float* q1 = q0 + 8 * (size_t)N3;
#pragma unroll
        for (int ks = 0; ks < 8; ks++) {
            qf[ks][0] = f2tf32(q0[ks * 8 + lk] * ATT_SCALE);
            qf[ks][1] = f2tf32(q1[ks * 8 + lk] * ATT_SCALE);
            qf[ks][2] = f2tf32(q0[ks * 8 + lk + 4] * ATT_SCALE);
            qf[ks][3] = f2tf32(q1[ks * 8 + lk + 4] * ATT_SCALE);
        }
    }

    float o[8][4];
#pragma unroll
    for (int nt = 0; nt < 8; nt++)
#pragma unroll
        for (int r = 0; r < 4; r++) o[nt][r] = 0.f;
    float m0 = -1e30f, m1 = -1e30f, l0 = 0.f, l1 = 0.f;

    const int ntiles = 2 * qb + 2;
    const int q0g = qb * 128 + wrow + lg;
    const int q1g = q0g + 8;

#pragma unroll 1
    for (int kb = 0; kb < ntiles; kb++) {
        CP_WAIT(0);
        __syncthreads();          // tile kb visible; all warps done with kb-1
        if (kb + 1 < ntiles) issue(kb + 1);

        const int buf = kb & 1;
        float (*Kb)[KS_STRIDE] = Ks[buf];
        float (*Vb)[VS_STRIDE] = Vs[buf];

        // ---- S = Q @ K^T ----
        float sa[8][4];
#pragma unroll
        for (int nt = 0; nt < 8; nt++)
#pragma unroll
            for (int r = 0; r < 4; r++) sa[nt][r] = 0.f;

#pragma unroll
        for (int ks = 0; ks < 8; ks++) {
#pragma unroll
            for (int nt = 0; nt < 8; nt++) {
                unsigned b0 = __float_as_uint(Kb[nt * 8 + lg][ks * 8 + lk]);
                unsigned b1 = __float_as_uint(Kb[nt * 8 + lg][ks * 8 + lk + 4]);
                MMA_TF32(sa[nt], qf[ks], b0, b1);
            }
        }

        // ---- causal mask ----
        if (kb * 64 + 63 > qb * 128 + wrow) {
#pragma unroll
            for (int nt = 0; nt < 8; nt++) {
                int kg = kb * 64 + nt * 8 + 2 * lk;
                sa[nt][0] = (kg     <= q0g) ? sa[nt][0] : -1e30f;
                sa[nt][1] = (kg + 1 <= q0g) ? sa[nt][1] : -1e30f;
                sa[nt][2] = (kg     <= q1g) ? sa[nt][2] : -1e30f;
                sa[nt][3] = (kg + 1 <= q1g) ? sa[nt][3] : -1e30f;
            }
        }

        // ---- online softmax ----
        float mt0 = -1e30f, mt1 = -1e30f;
#pragma unroll
        for (int nt = 0; nt < 8; nt++) {
            mt0 = fmaxf(mt0, fmaxf(sa[nt][0], sa[nt][1]));
            mt1 = fmaxf(mt1, fmaxf(sa[nt][2], sa[nt][3]));
        }
        mt0 = fmaxf(mt0, __shfl_xor_sync(0xffffffff, mt0, 1));
        mt0 = fmaxf(mt0, __shfl_xor_sync(0xffffffff, mt0, 2));
        mt1 = fmaxf(mt1, __shfl_xor_sync(0xffffffff, mt1, 1));
        mt1 = fmaxf(mt1, __shfl_xor_sync(0xffffffff, mt1, 2));

        float mn0 = fmaxf(m0, mt0), mn1 = fmaxf(m1, mt1);
        float sc0 = __expf(m0 - mn0), sc1 = __expf(m1 - mn1);
        m0 = mn0; m1 = mn1;

#pragma unroll
        for (int nt = 0; nt < 8; nt++) {
            o[nt][0] *= sc0; o[nt][1] *= sc0;
            o[nt][2] *= sc1; o[nt][3] *= sc1;
        }

        float s0 = 0.f, s1 = 0.f;
#pragma unroll
        for (int nt = 0; nt < 8; nt++) {
            float p0 = __expf(sa[nt][0] - mn0);
            float p1 = __expf(sa[nt][1] - mn0);
            float p2 = __expf(sa[nt][2] - mn1);
            float p3 = __expf(sa[nt][3] - mn1);
            s0 += p0 + p1; s1 += p2 + p3;
            float2 v0, v1;
            v0.x = __uint_as_float(f2tf32(p0));
            v0.y = __uint_as_float(f2tf32(p1));
            v1.x = __uint_as_float(f2tf32(p2));
            v1.y = __uint_as_float(f2tf32(p3));
            *(float2*)(&Ps[wrow + lg][nt * 8 + 2 * lk]) = v0;
            *(float2*)(&Ps[wrow + 8 + lg][nt * 8 + 2 * lk]) = v1;
        }
        s0 += __shfl_xor_sync(0xffffffff, s0, 1);
        s0 += __shfl_xor_sync(0xffffffff, s0, 2);
        s1 += __shfl_xor_sync(0xffffffff, s1, 1);
        s1 += __shfl_xor_sync(0xffffffff, s1, 2);
        l0 = l0 * sc0 + s0;
        l1 = l1 * sc1 + s1;

        __syncwarp();

        // ---- O += P @ V ----
#pragma unroll
        for (int ks = 0; ks < 8; ks++) {
            unsigned af[4];
            af[0] = __float_as_uint(Ps[wrow + lg][ks * 8 + lk]);
            af[1] = __float_as_uint(Ps[wrow + 8 + lg][ks * 8 + lk]);
            af[2] = __float_as_uint(Ps[wrow + lg][ks * 8 + lk + 4]);
            af[3] = __float_as_uint(Ps[wrow + 8 + lg][ks * 8 + lk + 4]);
#pragma unroll
            for (int nt = 0; nt < 8; nt++) {
                unsigned b0 = __float_as_uint(Vb[ks * 8 + lk][nt * 8 + lg]);
                unsigned b1 = __float_as_uint(Vb[ks * 8 + lk + 4][nt * 8 + lg]);
                MMA_TF32(o[nt], af, b0, b1);
            }
        }
    }

    // ---- epilogue (round y to tf32 for the projection GEMM) ----
    float i0 = 1.f / l0, i1 = 1.f / l1;
    float* y0 = y + ((size_t)b * Tt + qb * 128 + wrow + lg) * Cc + h * Dd;
    float* y1 = y0 + 8 * (size_t)Cc;
#pragma unroll
    for (int nt = 0; nt < 8; nt++) {
        float2 w0, w1;
        w0.x = __uint_as_float(f2tf32(o[nt][0] * i0));
        w0.y = __uint_as_float(f2tf32(o[nt][1] * i0));
        w1.x = __uint_as_float(f2tf32(o[nt][2] * i1));
        w1.y = __uint_as_float(f2tf32(o[nt][3] * i1));
        *(float2*)(y0 + nt * 8 + 2 * lk) = w0;
        *(float2*)(y1 + nt * 8 + 2 * lk) = w1;
    }
}

// ---------------------------------------------------------------------------
extern "C" void kernel_launch(void* const* d_in, const int* in_sizes, int n_in,
                              void* d_out, int out_size)
{
    const float* x      = (const float*)d_in[0];
    const float* w_attn = (const float*)d_in[1];
    const float* b_attn = (const float*)d_in[2];
    const float* w_proj = (const float*)d_in[3];
    const float* b_proj = (const float*)d_in[4];
    float* out = (float*)d_out;

    void *qkv_p, *y_p, *xr_p, *war_p, *wpr_p;
    cudaGetSymbolAddress(&qkv_p, g_qkv);
    cudaGetSymbolAddress(&y_p, g_y);
    cudaGetSymbolAddress(&xr_p, g_xr);
    cudaGetSymbolAddress(&war_p, g_war);
    cudaGetSymbolAddress(&wpr_p, g_wpr);
    float* qkv = (float*)qkv_p;
    float* y   = (float*)y_p;
    float* xr  = (float*)xr_p;
    float* war = (float*)war_p;
    float* wpr = (float*)wpr_p;

    static bool attr_set = false;
    if (!attr_set) {
        cudaFuncSetAttribute(attn_tc_kernel,
                             cudaFuncAttributeMaxDynamicSharedMemorySize,
                             SMEM_ATTN);
        cudaFuncSetAttribute(gemm_tf32_bias_kernel,
                             cudaFuncAttributeMaxDynamicSharedMemorySize,
                             SMEM_GEMM);
        attr_set = true;
    }

    // 0) pre-round GEMM inputs to tf32
    cvt_tf32_kernel<<<1024, 256>>>(x, xr, Mm * Cc / 4);
    cvt_tf32_kernel<<<1024, 256>>>(w_attn, war, Cc * N3 / 4);
    cvt_tf32_kernel<<<1024, 256>>>(w_proj, wpr, Cc * Cc / 4);

    // 1) qkv = xr @ war + b_attn  (output rounded to tf32)
    {
        dim3 grid(N3 / 128, Mm / 128);
        gemm_tf32_bias_kernel<<<grid, 256, SMEM_GEMM>>>(
            xr, war, b_attn, qkv, Mm, N3, Cc, 1);
    }
    // 2) causal attention -> y (rounded to tf32)
    {
        dim3 grid(Tt / 128, Bt * Hh);
        attn_tc_kernel<<<grid, 256, SMEM_ATTN>>>(qkv, y);
    }
    // 3) out = y @ wpr + b_proj  (full fp32 output)
    {
        dim3 grid(Cc / 128, Mm / 128);
        gemm_tf32_bias_kernel<<<grid, 256, SMEM_GEMM>>>(
            y, wpr, b_proj, out, Mm, Cc, Cc, 0);
    }
}